// round 4
// baseline (speedup 1.0000x reference)
#include <cuda_runtime.h>
#include <cstdint>

#define L     2048
#define HOUT  96
#define ROWS  64      // C-tile rows per block
#define BK    16      // K chunk
#define TPB   256

// packed fp32x2 FMA: c = a*b + c  (2 FMAs per instruction on sm_103a)
__device__ __forceinline__ void fma2(float2& c, const float2 a, const float2 b) {
    asm("fma.rn.f32x2 %0, %1, %2, %0;"
        : "+l"(*reinterpret_cast<unsigned long long*>(&c))
        : "l"(reinterpret_cast<const unsigned long long&>(a)),
          "l"(reinterpret_cast<const unsigned long long&>(b)));
}

union SmemU {
    struct {
        float  a[BK][ROWS];       // A chunk, transposed: [kk][row]
        float2 b[BK][HOUT];       // B chunk, each entry duplicated (w,w)
    } g;
    float tail[ROWS][153];        // last 152 cols of x per row (stride 153: conflict-free)
};

extern "C" __global__ void __launch_bounds__(TPB, 2)
ar2_fused_kernel(const float* __restrict__ x, const float* __restrict__ W,
                 float* __restrict__ out)
{
    const int tid  = threadIdx.x;
    const int rg   = tid & 15;        // row-group 0..15 (4 rows each)
    const int cg   = tid >> 4;        // col-group 0..15 (6 cols each)
    const int row0 = blockIdx.x * ROWS;

    __shared__ SmemU u;
    __shared__ float2 sums_s[ROWS];                         // (sum, sumsq) per row
    __shared__ float rp_a1[ROWS], rp_a2[ROWS], rp_y1[ROWS],
                     rp_y2[ROWS], rp_lo[ROWS], rp_hi[ROWS];

    // ---- GEMM accumulators: 4 rows x 6 cols as 2x6 packed pairs ----
    float2 acc[2][6];
#pragma unroll
    for (int p = 0; p < 2; p++)
#pragma unroll
        for (int c = 0; c < 6; c++) acc[p][c] = make_float2(0.f, 0.f);

    // A loader mapping: thread -> (row, 4-col segment)
    const int arow = tid >> 2;              // 0..63
    const int ac4  = (tid & 3) << 2;        // 0,4,8,12
    const float* aptr = x + (size_t)(row0 + arow) * L + ac4;

    float s1 = 0.f, s2 = 0.f;               // per-thread partial sum / sumsq

    // ---- prefetch chunk 0 ----
    float4 aReg = *(const float4*)(aptr);
    float2 bReg[3];
#pragma unroll
    for (int it = 0; it < 3; it++) {
        int idx = tid + it * TPB;           // 0..767
        int k = idx / 48, c2 = idx % 48;
        bReg[it] = *(const float2*)(W + k * HOUT + 2 * c2);
    }

    for (int k0 = 0; k0 < L; k0 += BK) {
        // store prefetched chunk to smem; fold stats off the A stream
#pragma unroll
        for (int i = 0; i < 4; i++)
            u.g.a[ac4 + i][arow] = (&aReg.x)[i];
        s1 += aReg.x + aReg.y + aReg.z + aReg.w;
        s2 += aReg.x*aReg.x + aReg.y*aReg.y + aReg.z*aReg.z + aReg.w*aReg.w;
#pragma unroll
        for (int it = 0; it < 3; it++) {
            int idx = tid + it * TPB;
            int k = idx / 48, c2 = (idx % 48) * 2;
            u.g.b[k][c2]     = make_float2(bReg[it].x, bReg[it].x);
            u.g.b[k][c2 + 1] = make_float2(bReg[it].y, bReg[it].y);
        }
        __syncthreads();

        // prefetch next chunk (overlaps with compute below)
        if (k0 + BK < L) {
            aReg = *(const float4*)(aptr + k0 + BK);
#pragma unroll
            for (int it = 0; it < 3; it++) {
                int idx = tid + it * TPB;
                int k = idx / 48, c2 = idx % 48;
                bReg[it] = *(const float2*)(W + (k0 + BK + k) * HOUT + 2 * c2);
            }
        }

        // inner product: 16 kk x (1 LDS.128 A + 3 LDS.128 B + 12 FFMA2)
#pragma unroll
        for (int kk = 0; kk < BK; kk++) {
            float4 av = *(const float4*)&u.g.a[kk][4 * rg];
            float2 a0 = make_float2(av.x, av.y);
            float2 a1 = make_float2(av.z, av.w);
#pragma unroll
            for (int t = 0; t < 3; t++) {
                float4 bv = *(const float4*)&u.g.b[kk][6 * cg + 2 * t];
                float2 blo = make_float2(bv.x, bv.y);   // (w_c, w_c)
                float2 bhi = make_float2(bv.z, bv.w);   // (w_{c+1}, w_{c+1})
                fma2(acc[0][2*t],     a0, blo);
                fma2(acc[0][2*t + 1], a0, bhi);
                fma2(acc[1][2*t],     a1, blo);
                fma2(acc[1][2*t + 1], a1, bhi);
            }
        }
        __syncthreads();
    }

    // ---- reduce stats across the 4 threads sharing a row (adjacent lanes) ----
    s1 += __shfl_xor_sync(0xffffffffu, s1, 1);
    s1 += __shfl_xor_sync(0xffffffffu, s1, 2);
    s2 += __shfl_xor_sync(0xffffffffu, s2, 1);
    s2 += __shfl_xor_sync(0xffffffffu, s2, 2);
    if ((tid & 3) == 0) sums_s[arow] = make_float2(s1, s2);

    // ---- load tail (last 152 cols) into union (GEMM smem now dead) ----
    for (int idx = tid; idx < ROWS * 38; idx += TPB) {
        int r = idx / 38, q = (idx % 38) * 4;
        float4 v = *(const float4*)(x + (size_t)(row0 + r) * L + (L - 152) + q);
        u.tail[r][q]     = v.x;
        u.tail[r][q + 1] = v.y;
        u.tail[r][q + 2] = v.z;
        u.tail[r][q + 3] = v.w;
    }
    __syncthreads();

    // ---- per-row AR2 fit + std bounds (threads 0..63) ----
    if (tid < ROWS) {
        const float* y = &u.tail[tid][2];   // y[0..149] = x[-150:]
        float A11 = 0.f, A22 = 0.f, A12 = 0.f, b1 = 0.f, b2 = 0.f;
        float ym2 = y[0], ym1 = y[1];
#pragma unroll 4
        for (int j = 2; j < 150; j++) {
            float yc = y[j];
            A22 = fmaf(ym2, ym2, A22);
            A11 = fmaf(ym1, ym1, A11);
            A12 = fmaf(ym1, ym2, A12);
            b1  = fmaf(ym1, yc, b1);
            b2  = fmaf(ym2, yc, b2);
            ym2 = ym1; ym1 = yc;
        }
        A11 += 0.001f; A22 += 0.001f;
        float det = A11 * A22 - A12 * A12;
        float inv = 1.0f / det;
        float a1c = (b1 * A22 - b2 * A12) * inv;
        float a2c = (A11 * b2 - A12 * b1) * inv;

        float2 s = sums_s[tid];
        float mean = s.x * (1.0f / 2048.0f);
        float var  = fmaxf((s.y - s.x * mean) * (1.0f / 2047.0f), 0.f);
        float hstd = fmaxf(sqrtf(var), 1e-6f);
        float last = y[149];

        rp_a1[tid] = a1c; rp_a2[tid] = a2c;
        rp_y1[tid] = y[149]; rp_y2[tid] = y[148];
        rp_lo[tid] = last - 4.0f * hstd;
        rp_hi[tid] = last + 4.0f * hstd;
    }
    __syncthreads();

    // ---- epilogue: forecast recurrence + add GEMM + clip + store ----
    const int h0 = 6 * cg;
#pragma unroll
    for (int ur = 0; ur < 4; ur++) {
        const int r  = 4 * rg + ur;
        const int p  = ur >> 1;     // which packed pair
        const int hf = ur & 1;      // which half of the pair
        float a1c = rp_a1[r], a2c = rp_a2[r];
        float y1 = rp_y1[r], y2 = rp_y2[r];
        float lo = rp_lo[r], hi = rp_hi[r];

        // advance recurrence to h0
        for (int h = 0; h < h0; h++) {
            float yn = fmaf(a1c, y1, a2c * y2);
            y2 = y1; y1 = yn;
        }
        float vout[6];
#pragma unroll
        for (int c = 0; c < 6; c++) {
            float yn = fmaf(a1c, y1, a2c * y2);
            y2 = y1; y1 = yn;
            float d = hf ? acc[p][c].y : acc[p][c].x;
            vout[c] = fminf(fmaxf(yn + d, lo), hi);
        }
        float* op = out + (size_t)(row0 + r) * HOUT + h0;
        *(float2*)(op)     = make_float2(vout[0], vout[1]);
        *(float2*)(op + 2) = make_float2(vout[2], vout[3]);
        *(float2*)(op + 4) = make_float2(vout[4], vout[5]);
    }
}

extern "C" void kernel_launch(void* const* d_in, const int* in_sizes, int n_in,
                              void* d_out, int out_size)
{
    const float* x = (const float*)d_in[0];
    const float* W = (const float*)d_in[1];
    // defensive: x is the big tensor
    if (n_in >= 2 && in_sizes[0] < in_sizes[1]) {
        const float* t = x; x = W; W = t;
    }
    float* out = (float*)d_out;

    const int rows_total = 32 * 512;            // 16384
    dim3 grid(rows_total / ROWS);               // 256 blocks
    ar2_fused_kernel<<<grid, TPB>>>(x, W, out);
}

// round 6
// speedup vs baseline: 2.6260x; 2.6260x over previous
#include <cuda_runtime.h>
#include <cuda_bf16.h>
#include <cstdint>

#define L      2048
#define HOUT   96
#define ROWS   128     // M-tile per block
#define BK     32      // K chunk
#define TPB    256

// ---------------- preprocessed W: transposed + bf16 hi/lo split ----------------
__device__ __align__(16) __nv_bfloat16 g_Wt_h[HOUT * L];   // [n][k]
__device__ __align__(16) __nv_bfloat16 g_Wt_l[HOUT * L];   // [n][k]

__global__ void __launch_bounds__(TPB)
prep_W_kernel(const float* __restrict__ W)
{
    __shared__ float s[32][97];
    const int k0 = blockIdx.x * 32;
    const int tid = threadIdx.x;
#pragma unroll
    for (int i = 0; i < 12; i++) {
        int idx = tid + i * TPB;            // 0..3071
        int k = idx / 96, n = idx % 96;
        s[k][n] = W[(size_t)(k0 + k) * 96 + n];
    }
    __syncthreads();
#pragma unroll
    for (int i = 0; i < 12; i++) {
        int idx = tid + i * TPB;
        int n = idx >> 5, k = idx & 31;
        float v = s[k][n];
        __nv_bfloat16 h = __float2bfloat16(v);
        __nv_bfloat16 lo = __float2bfloat16(v - __bfloat162float(h));
        g_Wt_h[(size_t)n * L + k0 + k] = h;
        g_Wt_l[(size_t)n * L + k0 + k] = lo;
    }
}

// ---------------- main fused kernel ----------------

#define ASTRIDE 40   // bf16 elems per smem row (32 data + 8 pad) -> 80B, conflict-free ldmatrix

struct GemmS {
    __nv_bfloat16 Ah[ROWS * ASTRIDE];   // 10240 B
    __nv_bfloat16 Al[ROWS * ASTRIDE];   // 10240 B
    __nv_bfloat16 Bh[HOUT * ASTRIDE];   //  7680 B
    __nv_bfloat16 Bl[HOUT * ASTRIDE];   //  7680 B
};
union SmemU {
    GemmS g;                  // 35840 B
    float tail[64 * 153];     // 39168 B (64 rows x 152 cols, stride 153)
};

__device__ __forceinline__ void ldsm4(uint32_t* d, uint32_t addr) {
    asm volatile("ldmatrix.sync.aligned.m8n8.x4.shared.b16 {%0,%1,%2,%3}, [%4];"
                 : "=r"(d[0]), "=r"(d[1]), "=r"(d[2]), "=r"(d[3]) : "r"(addr));
}
__device__ __forceinline__ void mma16816(float* c, const uint32_t* a, const uint32_t* b) {
    asm volatile("mma.sync.aligned.m16n8k16.row.col.f32.bf16.bf16.f32 "
                 "{%0,%1,%2,%3}, {%4,%5,%6,%7}, {%8,%9}, {%0,%1,%2,%3};"
                 : "+f"(c[0]), "+f"(c[1]), "+f"(c[2]), "+f"(c[3])
                 : "r"(a[0]), "r"(a[1]), "r"(a[2]), "r"(a[3]), "r"(b[0]), "r"(b[1]));
}

extern "C" __global__ void __launch_bounds__(TPB, 1)
ar2_mma_kernel(const float* __restrict__ x, float* __restrict__ out)
{
    const int tid = threadIdx.x;
    const int lane = tid & 31;
    const int w    = tid >> 5;        // 0..7
    const int wm   = w & 3;           // M group (32 rows)
    const int wn   = w >> 2;          // N group (48 cols)
    const int row0 = blockIdx.x * ROWS;

    __shared__ SmemU u;
    __shared__ float st_s1[ROWS], st_s2[ROWS];
    __shared__ float rp_a1[ROWS], rp_a2[ROWS], rp_y1[ROWS],
                     rp_y2[ROWS], rp_lo[ROWS], rp_hi[ROWS];

    // C fragments: [m-tile 0/1][n-tile 0..5][c0..c3]
    float acc[2][6][4];
#pragma unroll
    for (int tm = 0; tm < 2; tm++)
#pragma unroll
        for (int tn = 0; tn < 6; tn++)
#pragma unroll
            for (int q = 0; q < 4; q++) acc[tm][tn][q] = 0.f;

    // ---- ldmatrix frag addresses (shared-space u32) ----
    const int aFragRow = wm * 32 + (lane & 15);
    const int aFragCol = (lane & 16) >> 1;          // 0 or 8 elems (k offset)
    const uint32_t aHaddr = (uint32_t)__cvta_generic_to_shared(u.g.Ah)
                          + (uint32_t)(aFragRow * ASTRIDE + aFragCol) * 2;
    const uint32_t aLaddr = (uint32_t)__cvta_generic_to_shared(u.g.Al)
                          + (uint32_t)(aFragRow * ASTRIDE + aFragCol) * 2;
    const int bFragRow = wn * 48 + ((lane >> 4) << 3) + (lane & 7);
    const int bFragCol = (lane & 8);                // 0 or 8 elems
    const uint32_t bHaddr = (uint32_t)__cvta_generic_to_shared(u.g.Bh)
                          + (uint32_t)(bFragRow * ASTRIDE + bFragCol) * 2;
    const uint32_t bLaddr = (uint32_t)__cvta_generic_to_shared(u.g.Bl)
                          + (uint32_t)(bFragRow * ASTRIDE + bFragCol) * 2;

    // ---- loader mappings ----
    // A: per chunk thread covers rows {i*32 + (tid>>3)}, float4 seg = tid&7 (coalesced 128B/row)
    const int aRow = tid >> 3;          // 0..31
    const int aSeg = tid & 7;           // 0..7 (x4 floats)
    // B: 768 float4 per chunk (hi 384, lo 384)
    float4 aReg[4];
    float4 bReg[3];
    float s1v[4] = {0.f, 0.f, 0.f, 0.f}, s2v[4] = {0.f, 0.f, 0.f, 0.f};

    // prefetch chunk 0
#pragma unroll
    for (int i = 0; i < 4; i++)
        aReg[i] = *(const float4*)(x + (size_t)(row0 + i * 32 + aRow) * L + aSeg * 4);
#pragma unroll
    for (int it = 0; it < 3; it++) {
        int idx = tid + it * TPB;
        int half = idx >= 384;
        int j = idx - half * 384;
        int n = j >> 2, seg = j & 3;
        const __nv_bfloat16* src = half ? g_Wt_l : g_Wt_h;
        bReg[it] = *(const float4*)(src + (size_t)n * L + seg * 8);
    }

    for (int k0 = 0; k0 < L; k0 += BK) {
        // ---- convert + store prefetched chunk; fold stats off A ----
#pragma unroll
        for (int i = 0; i < 4; i++) {
            float4 v = aReg[i];
            s1v[i] += v.x + v.y + v.z + v.w;
            s2v[i] += v.x * v.x + v.y * v.y + v.z * v.z + v.w * v.w;
            __nv_bfloat162 H0 = __float22bfloat162_rn(make_float2(v.x, v.y));
            __nv_bfloat162 H1 = __float22bfloat162_rn(make_float2(v.z, v.w));
            float2 hf0 = __bfloat1622float2(H0);
            float2 hf1 = __bfloat1622float2(H1);
            __nv_bfloat162 L0 = __float22bfloat162_rn(make_float2(v.x - hf0.x, v.y - hf0.y));
            __nv_bfloat162 L1 = __float22bfloat162_rn(make_float2(v.z - hf1.x, v.w - hf1.y));
            int off = (i * 32 + aRow) * ASTRIDE + aSeg * 4;
            *reinterpret_cast<uint2*>(&u.g.Ah[off]) =
                make_uint2(reinterpret_cast<uint32_t&>(H0), reinterpret_cast<uint32_t&>(H1));
            *reinterpret_cast<uint2*>(&u.g.Al[off]) =
                make_uint2(reinterpret_cast<uint32_t&>(L0), reinterpret_cast<uint32_t&>(L1));
        }
#pragma unroll
        for (int it = 0; it < 3; it++) {
            int idx = tid + it * TPB;
            int half = idx >= 384;
            int j = idx - half * 384;
            int n = j >> 2, seg = j & 3;
            __nv_bfloat16* dst = half ? u.g.Bl : u.g.Bh;
            *(float4*)(dst + n * ASTRIDE + seg * 8) = bReg[it];
        }
        __syncthreads();

        // ---- prefetch next chunk (overlaps mma below) ----
        if (k0 + BK < L) {
#pragma unroll
            for (int i = 0; i < 4; i++)
                aReg[i] = *(const float4*)(x + (size_t)(row0 + i * 32 + aRow) * L
                                           + (k0 + BK) + aSeg * 4);
#pragma unroll
            for (int it = 0; it < 3; it++) {
                int idx = tid + it * TPB;
                int half = idx >= 384;
                int j = idx - half * 384;
                int n = j >> 2, seg = j & 3;
                const __nv_bfloat16* src = half ? g_Wt_l : g_Wt_h;
                bReg[it] = *(const float4*)(src + (size_t)n * L + (k0 + BK) + seg * 8);
            }
        }

        // ---- tensor compute: 2 k16 steps ----
#pragma unroll
        for (int ks = 0; ks < 2; ks++) {
            uint32_t aH[2][4], aL[2][4], bH[3][4], bL[3][4];
#pragma unroll
            for (int tm = 0; tm < 2; tm++) {
                uint32_t off = (uint32_t)(tm * 16 * ASTRIDE + ks * 16) * 2;
                ldsm4(aH[tm], aHaddr + off);
                ldsm4(aL[tm], aLaddr + off);
            }
#pragma unroll
            for (int np = 0; np < 3; np++) {
                uint32_t off = (uint32_t)(np * 16 * ASTRIDE + ks * 16) * 2;
                ldsm4(bH[np], bHaddr + off);
                ldsm4(bL[np], bLaddr + off);
            }
#pragma unroll
            for (int tm = 0; tm < 2; tm++)
#pragma unroll
                for (int tn = 0; tn < 6; tn++) {
                    const uint32_t* bh = &bH[tn >> 1][(tn & 1) * 2];
                    const uint32_t* bl = &bL[tn >> 1][(tn & 1) * 2];
                    mma16816(acc[tm][tn], aH[tm], bh);   // hi*hi
                    mma16816(acc[tm][tn], aH[tm], bl);   // hi*lo
                    mma16816(acc[tm][tn], aL[tm], bh);   // lo*hi
                }
        }
        __syncthreads();
    }

    // ---- stats reduce: 8 lanes share each row (same tid>>3 group) ----
#pragma unroll
    for (int i = 0; i < 4; i++) {
        s1v[i] += __shfl_xor_sync(0xffffffffu, s1v[i], 1);
        s1v[i] += __shfl_xor_sync(0xffffffffu, s1v[i], 2);
        s1v[i] += __shfl_xor_sync(0xffffffffu, s1v[i], 4);
        s2v[i] += __shfl_xor_sync(0xffffffffu, s2v[i], 1);
        s2v[i] += __shfl_xor_sync(0xffffffffu, s2v[i], 2);
        s2v[i] += __shfl_xor_sync(0xffffffffu, s2v[i], 4);
    }
    if ((tid & 7) == 0) {
#pragma unroll
        for (int i = 0; i < 4; i++) {
            st_s1[i * 32 + aRow] = s1v[i];
            st_s2[i * 32 + aRow] = s2v[i];
        }
    }

    // ---- tail staging + AR2 fit, two passes of 64 rows through the union ----
    for (int pass = 0; pass < 2; pass++) {
        __syncthreads();   // previous union use done (gemm smem / prior tail)
        const int rbase = pass * 64;
        for (int idx = tid; idx < 64 * 38; idx += TPB) {
            int r = idx / 38, q = (idx % 38) * 4;
            float4 v = *(const float4*)(x + (size_t)(row0 + rbase + r) * L + (L - 152) + q);
            float* tp = &u.tail[r * 153];
            tp[q] = v.x; tp[q + 1] = v.y; tp[q + 2] = v.z; tp[q + 3] = v.w;
        }
        __syncthreads();
        if (tid < 64) {
            const int r = rbase + tid;
            const float* y = &u.tail[tid * 153 + 2];   // y[0..149] = x[-150:]
            float A11 = 0.f, A22 = 0.f, A12 = 0.f, b1 = 0.f, b2 = 0.f;
            float ym2 = y[0], ym1 = y[1];
#pragma unroll 4
            for (int j = 2; j < 150; j++) {
                float yc = y[j];
                A22 = fmaf(ym2, ym2, A22);
                A11 = fmaf(ym1, ym1, A11);
                A12 = fmaf(ym1, ym2, A12);
                b1  = fmaf(ym1, yc, b1);
                b2  = fmaf(ym2, yc, b2);
                ym2 = ym1; ym1 = yc;
            }
            A11 += 0.001f; A22 += 0.001f;
            float det = A11 * A22 - A12 * A12;
            float inv = 1.0f / det;
            float a1c = (b1 * A22 - b2 * A12) * inv;
            float a2c = (A11 * b2 - A12 * b1) * inv;

            float s1 = st_s1[r], s2 = st_s2[r];
            float mean = s1 * (1.0f / 2048.0f);
            float var  = fmaxf((s2 - s1 * mean) * (1.0f / 2047.0f), 0.f);
            float hstd = fmaxf(sqrtf(var), 1e-6f);
            float last = y[149];

            rp_a1[r] = a1c; rp_a2[r] = a2c;
            rp_y1[r] = y[149]; rp_y2[r] = y[148];
            rp_lo[r] = last - 4.0f * hstd;
            rp_hi[r] = last + 4.0f * hstd;
        }
    }
    __syncthreads();

    // ---- epilogue: forecast walk + add GEMM + clip + store ----
    const int cbase = wn * 48 + 2 * (lane & 3);
#pragma unroll
    for (int tm = 0; tm < 2; tm++) {
#pragma unroll
        for (int half = 0; half < 2; half++) {
            const int r = wm * 32 + tm * 16 + (lane >> 2) + half * 8;
            float a1c = rp_a1[r], a2c = rp_a2[r];
            float y1 = rp_y1[r], y2 = rp_y2[r];
            float lo = rp_lo[r], hi = rp_hi[r];
            int h = 0;
            float* op = out + (size_t)(row0 + r) * HOUT;
#pragma unroll
            for (int tn = 0; tn < 6; tn++) {
                const int target = cbase + tn * 8 + 1;   // steps for first col of pair
                while (h < target) {
                    float yn = fmaf(a1c, y1, a2c * y2);
                    y2 = y1; y1 = yn; h++;
                }
                float v0 = y1;
                { float yn = fmaf(a1c, y1, a2c * y2); y2 = y1; y1 = yn; h++; }
                float v1 = y1;
                float o0 = fminf(fmaxf(v0 + acc[tm][tn][half * 2 + 0], lo), hi);
                float o1 = fminf(fmaxf(v1 + acc[tm][tn][half * 2 + 1], lo), hi);
                *(float2*)(op + cbase + tn * 8) = make_float2(o0, o1);
            }
        }
    }
}

extern "C" void kernel_launch(void* const* d_in, const int* in_sizes, int n_in,
                              void* d_out, int out_size)
{
    const float* x = (const float*)d_in[0];
    const float* W = (const float*)d_in[1];
    if (n_in >= 2 && in_sizes[0] < in_sizes[1]) {   // defensive: x is the big tensor
        const float* t = x; x = W; W = t;
    }
    float* out = (float*)d_out;

    prep_W_kernel<<<L / 32, TPB>>>(W);              // 64 blocks: transpose + hi/lo split
    ar2_mma_kernel<<<(32 * 512) / ROWS, TPB>>>(x, out);   // 128 blocks
}